// round 15
// baseline (speedup 1.0000x reference)
#include <cuda_runtime.h>
#include <cuda_bf16.h>
#include <cstdint>

typedef unsigned long long ull;

// Problem constants
#define BB    64    // batch
#define WDIM  128   // node feature dim (K of projection)
#define FDIM  64    // number of nodes
#define HH    4     // heads
#define DOUT  128   // out window per head

// Scratch (device globals; allocation-free)
__device__ float g_fs[BB * HH * FDIM * DOUT];   // [b][h][i][d]
__device__ float g_fd[BB * HH * FDIM * DOUT];   // [b][h][j][d]
__device__ float g_oh[BB * HH * FDIM * DOUT];   // [b][h][j][d] per-head outputs

// Fragment-ordered bf16 hi/lo operands for mma.sync m16n8k16.
// One uint4 (16B) per (row, s, u):  {pair(k0,k0+1) hi, pair(k0+8,k0+9) hi,
//                                    pair(k0,k0+1) lo, pair(k0+8,k0+9) lo}
// with k0 = 16*s + 2*u.  Index = row*32 + s*4 + u.
__device__ uint4 g_a[4096 * 32];   // A = X^T rows [b*64+f], k = w
__device__ uint4 g_w[1024 * 32];   // rows 0..511 = Wsrc, 512..1023 = Wdst

// ---------------------------------------------------------------------------
// f32x2 packed-math helpers (attn kernel)
// ---------------------------------------------------------------------------
__device__ __forceinline__ ull fma2(ull a, ull b, ull c) {
    asm("fma.rn.f32x2 %0, %1, %2, %0;" : "+l"(c) : "l"(a), "l"(b));
    return c;
}
__device__ __forceinline__ ull add2(ull a, ull b) {
    ull d; asm("add.rn.f32x2 %0, %1, %2;" : "=l"(d) : "l"(a), "l"(b));
    return d;
}
__device__ __forceinline__ float2 u2f(ull v) {
    float2 f; asm("mov.b64 {%0, %1}, %2;" : "=f"(f.x), "=f"(f.y) : "l"(v));
    return f;
}
__device__ __forceinline__ ull abs2(ull v) { return v & 0x7fffffff7fffffffULL; }

// ---------------------------------------------------------------------------
// bf16 pack helper: 4 floats -> {hi pair01, hi pair23, lo pair01, lo pair23}
// ---------------------------------------------------------------------------
__device__ __forceinline__ uint4 pack_hilo(float v0, float v1, float v2, float v3) {
    __nv_bfloat16 h0 = __float2bfloat16(v0), h1 = __float2bfloat16(v1);
    __nv_bfloat16 h2 = __float2bfloat16(v2), h3 = __float2bfloat16(v3);
    __nv_bfloat16 l0 = __float2bfloat16(v0 - __bfloat162float(h0));
    __nv_bfloat16 l1 = __float2bfloat16(v1 - __bfloat162float(h1));
    __nv_bfloat16 l2 = __float2bfloat16(v2 - __bfloat162float(h2));
    __nv_bfloat16 l3 = __float2bfloat16(v3 - __bfloat162float(h3));
    uint4 r;
    r.x = (uint32_t)__bfloat16_as_ushort(h0) | ((uint32_t)__bfloat16_as_ushort(h1) << 16);
    r.y = (uint32_t)__bfloat16_as_ushort(h2) | ((uint32_t)__bfloat16_as_ushort(h3) << 16);
    r.z = (uint32_t)__bfloat16_as_ushort(l0) | ((uint32_t)__bfloat16_as_ushort(l1) << 16);
    r.w = (uint32_t)__bfloat16_as_ushort(l2) | ((uint32_t)__bfloat16_as_ushort(l3) << 16);
    return r;
}

// mma.sync m16n8k16 row.col f32.bf16.bf16.f32, accumulate in place
__device__ __forceinline__ void mma_bf16(float* d, uint32_t a0, uint32_t a1,
                                         uint32_t a2, uint32_t a3,
                                         uint32_t b0, uint32_t b1) {
    asm volatile(
        "mma.sync.aligned.m16n8k16.row.col.f32.bf16.bf16.f32 "
        "{%0,%1,%2,%3}, {%4,%5,%6,%7}, {%8,%9}, {%0,%1,%2,%3};"
        : "+f"(d[0]), "+f"(d[1]), "+f"(d[2]), "+f"(d[3])
        : "r"(a0), "r"(a1), "r"(a2), "r"(a3), "r"(b0), "r"(b1));
}

// ---------------------------------------------------------------------------
// conv_w: W fp32 -> fragment-ordered bf16 hi/lo.  32768 blocks of 16B.
// ---------------------------------------------------------------------------
__global__ __launch_bounds__(256)
void conv_w(const float* __restrict__ Wsrc, const float* __restrict__ Wdst)
{
    int q  = blockIdx.x * 256 + threadIdx.x;   // 0..32767
    int n  = q >> 5, r5 = q & 31;
    int s  = r5 >> 2, u = r5 & 3;
    int k0 = 16 * s + 2 * u;
    const float* row = (n < 512) ? Wsrc + (size_t)n * 128
                                 : Wdst + (size_t)(n - 512) * 128;
    float2 pa = *(const float2*)(row + k0);
    float2 pb = *(const float2*)(row + k0 + 8);
    g_w[q] = pack_hilo(pa.x, pa.y, pb.x, pb.y);
}

// ---------------------------------------------------------------------------
// conv_x: x[b][w][f] fp32 -> A rows [b*64+f][k=w], fragment-ordered hi/lo.
// ---------------------------------------------------------------------------
__global__ __launch_bounds__(256)
void conv_x(const float* __restrict__ x)
{
    __shared__ float sm[128 * 65];
    const int b = blockIdx.x, t = threadIdx.x;
    const float* xb = x + (size_t)b * 8192;
    for (int idx = t; idx < 8192; idx += 256) {
        int w = idx >> 6, f = idx & 63;
        sm[w * 65 + f] = xb[idx];
    }
    __syncthreads();
    #pragma unroll
    for (int it = 0; it < 8; it++) {
        int q  = it * 256 + t;        // 0..2047
        int f  = q >> 5, r5 = q & 31;
        int s  = r5 >> 2, u = r5 & 3;
        int k0 = 16 * s + 2 * u;
        float v0 = sm[(k0)     * 65 + f];
        float v1 = sm[(k0 + 1) * 65 + f];
        float v2 = sm[(k0 + 8) * 65 + f];
        float v3 = sm[(k0 + 9) * 65 + f];
        g_a[(size_t)(b * 64 + f) * 32 + r5] = pack_hilo(v0, v1, v2, v3);
    }
}

// ---------------------------------------------------------------------------
// proj_mma: C[4096,1024] = A @ Wcat^T via bf16 HMMA with hi/lo compensation.
// (unchanged from R11 — validated)
// ---------------------------------------------------------------------------
__global__ __launch_bounds__(256)
void proj_mma(const float* __restrict__ bsrc, const float* __restrict__ bdst)
{
    const int t    = threadIdx.x;
    const int w    = t >> 5;
    const int lane = t & 31;
    const int g    = lane >> 2;
    const int tt   = lane & 3;

    const int rowBase = blockIdx.x * 64  + (w >> 2) * 32;
    const int colBase = blockIdx.y * 128 + (w & 3) * 32;

    float acc[2][4][4];
    #pragma unroll
    for (int mf = 0; mf < 2; mf++)
        #pragma unroll
        for (int nf = 0; nf < 4; nf++)
            #pragma unroll
            for (int e = 0; e < 4; e++) acc[mf][nf][e] = 0.f;

    #pragma unroll
    for (int s = 0; s < 8; s++) {
        uint4 a[2][2];
        #pragma unroll
        for (int mf = 0; mf < 2; mf++) {
            int r0 = rowBase + mf * 16 + g;
            a[mf][0] = g_a[(size_t)r0 * 32 + s * 4 + tt];
            a[mf][1] = g_a[(size_t)(r0 + 8) * 32 + s * 4 + tt];
        }
        uint4 bf[4];
        #pragma unroll
        for (int nf = 0; nf < 4; nf++) {
            int n0 = colBase + nf * 8 + g;
            bf[nf] = g_w[(size_t)n0 * 32 + s * 4 + tt];
        }
        #pragma unroll
        for (int mf = 0; mf < 2; mf++)
            #pragma unroll
            for (int nf = 0; nf < 4; nf++) {
                mma_bf16(acc[mf][nf], a[mf][0].x, a[mf][1].x, a[mf][0].y, a[mf][1].y,
                         bf[nf].x, bf[nf].y);
                mma_bf16(acc[mf][nf], a[mf][0].x, a[mf][1].x, a[mf][0].y, a[mf][1].y,
                         bf[nf].z, bf[nf].w);
                mma_bf16(acc[mf][nf], a[mf][0].z, a[mf][1].z, a[mf][0].w, a[mf][1].w,
                         bf[nf].x, bf[nf].y);
            }
    }

    const bool is_fs = (colBase < 512);
    const float* bias = is_fs ? bsrc : bdst;
    #pragma unroll
    for (int nf = 0; nf < 4; nf++) {
        int cg   = colBase + nf * 8 + 2 * tt;
        int head = (cg >> 7) & 3;
        int d    = cg & 127;
        int bidx = cg & 511;
        float2 bv = *(const float2*)(bias + bidx);
        float* arr = is_fs ? g_fs : g_fd;
        #pragma unroll
        for (int mf = 0; mf < 2; mf++) {
            int r = rowBase + mf * 16 + g;
            int bb = r >> 6, ff = r & 63;
            float* base = arr + ((size_t)(bb * 4 + head) * 64 + ff) * 128 + d;
            *(float2*)base = make_float2(acc[mf][nf][0] + bv.x, acc[mf][nf][1] + bv.y);
            float* base8 = base + 8 * 128;
            *(float2*)base8 = make_float2(acc[mf][nf][2] + bv.x, acc[mf][nf][3] + bv.y);
        }
    }
}

// ---------------------------------------------------------------------------
// Kernel 2: fused scores + softmax + HMMA aggregation, one CTA per (b,h).
// score rewrite: sum_d a_d*lrelu(fs+fd) = 0.6*(As[i]+Ad[j]) + sum_d (0.4 a_d)|fs+fd|
// Aggregation O[j,d] = sum_i P[j,i]*Fs[i,d] via m16n8k16 bf16 hi/lo
// (3 passes: PhFh + PhFl + PlFh).  Fragment arrays ALIAS prob (A) and fdN (B)
// after those regions go dead; reg-staged conversion with 3 syncthreads.
// ---------------------------------------------------------------------------
#define NSTRIDE 130

__global__ __launch_bounds__(256, 2)
void attn_kernel(const float* __restrict__ attn)
{
    extern __shared__ float sm[];
    float* fsN   = sm;                     // [64 i][130]               (8320)
    float* fdN   = sm + 8320;              // [64 j][130]; Bfrag after  (8320)
    float* attn4 = sm + 16640;             // 128  (0.4 * attn[h])
    float* attnv = attn4 + 128;            // 128
    float* As_s  = attnv + 128;            // 64
    float* Ad_s  = As_s + 64;              // 64
    float* prob  = Ad_s + 64;              // [64 j][64 i]; Afrag after (4096)

    const int bh   = blockIdx.x;
    const int h    = bh & 3;
    const int t    = threadIdx.x;
    const int lane = t & 31;
    const int w    = t >> 5;
    const int g    = lane >> 2;
    const int tt   = lane & 3;

    const float* fs = g_fs + (size_t)bh * FDIM * DOUT;
    const float* fd = g_fd + (size_t)bh * FDIM * DOUT;

    for (int p = t; p < FDIM * 64; p += 256) {
        int i = p >> 6, dp = p & 63;
        *(ull*)&fsN[i * NSTRIDE + 2 * dp] = *(const ull*)&fs[i * DOUT + 2 * dp];
        *(ull*)&fdN[i * NSTRIDE + 2 * dp] = *(const ull*)&fd[i * DOUT + 2 * dp];
    }
    if (t < 128) {
        float a = attn[h * 128 + t];
        attnv[t] = a;
        attn4[t] = 0.4f * a;
    }
    __syncthreads();

    if (t < 64) {
        float s = 0.f;
        #pragma unroll 4
        for (int d = 0; d < 128; d++) s = fmaf(attnv[d], fsN[t * NSTRIDE + d], s);
        As_s[t] = s;
    } else if (t < 128) {
        int j = t - 64;
        float s = 0.f;
        #pragma unroll 4
        for (int d = 0; d < 128; d++) s = fmaf(attnv[d], fdN[j * NSTRIDE + d], s);
        Ad_s[j] = s;
    }
    __syncthreads();

    // ---- Score phase: warp w owns j = w*8..w*8+7; lane owns i = lane, lane+32.
    const int jb = w * 8;
    const int i0 = lane, i1 = lane + 32;
    ull acc0[8], acc1[8];
    #pragma unroll
    for (int jj = 0; jj < 8; jj++) { acc0[jj] = 0ULL; acc1[jj] = 0ULL; }

    #pragma unroll 2
    for (int dp = 0; dp < 64; dp++) {
        ull a42 = *(const ull*)&attn4[2 * dp];
        ull f20 = *(const ull*)&fsN[i0 * NSTRIDE + 2 * dp];
        ull f21 = *(const ull*)&fsN[i1 * NSTRIDE + 2 * dp];
        #pragma unroll
        for (int jj = 0; jj < 8; jj++) {
            ull fd2 = *(const ull*)&fdN[(jb + jj) * NSTRIDE + 2 * dp];
            acc0[jj] = fma2(a42, abs2(add2(f20, fd2)), acc0[jj]);
            acc1[jj] = fma2(a42, abs2(add2(f21, fd2)), acc1[jj]);
        }
    }

    // ---- Softmax over i (64 sources) per j
    const float As0 = As_s[i0], As1 = As_s[i1];
    #pragma unroll
    for (int jj = 0; jj < 8; jj++) {
        float Adv = Ad_s[jb + jj];
        float2 h0 = u2f(acc0[jj]);
        float2 h1 = u2f(acc1[jj]);
        float s0 = 0.6f * (As0 + Adv) + (h0.x + h0.y);
        float s1 = 0.6f * (As1 + Adv) + (h1.x + h1.y);
        float m = fmaxf(s0, s1);
        #pragma unroll
        for (int o = 16; o; o >>= 1) m = fmaxf(m, __shfl_xor_sync(0xffffffffu, m, o));
        float e0 = __expf(s0 - m);
        float e1 = __expf(s1 - m);
        float ssum = e0 + e1;
        #pragma unroll
        for (int o = 16; o; o >>= 1) ssum += __shfl_xor_sync(0xffffffffu, ssum, o);
        float inv = __frcp_rn(ssum);
        prob[(jb + jj) * 64 + i0] = e0 * inv;
        prob[(jb + jj) * 64 + i1] = e1 * inv;
    }
    __syncthreads();   // all prob written; all score-phase fdN reads done

    // ---- Fragment conversion (reg-staged; aliases prob -> Afrag, fdN -> Bfrag)
    // Afrag: 1024 uint4, index j*16 + s*4 + u, k0 = 16s+2u (k = i)
    // Bfrag: 2048 uint4, index d*16 + s*4 + u, values Fs[k0..][d] (B col-major)
    uint4 aW[4], bW[8];
    #pragma unroll
    for (int e = 0; e < 4; e++) {
        int q = t * 4 + e;
        int j = q >> 4, su = q & 15;
        int k0 = 16 * (su >> 2) + 2 * (su & 3);
        const float* pr = prob + j * 64 + k0;
        aW[e] = pack_hilo(pr[0], pr[1], pr[8], pr[9]);
    }
    #pragma unroll
    for (int e = 0; e < 8; e++) {
        int q = t * 8 + e;
        int n = q >> 4, su = q & 15;
        int k0 = 16 * (su >> 2) + 2 * (su & 3);
        bW[e] = pack_hilo(fsN[k0 * NSTRIDE + n],       fsN[(k0 + 1) * NSTRIDE + n],
                          fsN[(k0 + 8) * NSTRIDE + n], fsN[(k0 + 9) * NSTRIDE + n]);
    }
    __syncthreads();   // all reads complete before aliasing writes
    uint4* Af = (uint4*)prob;
    uint4* Bf = (uint4*)fdN;
    #pragma unroll
    for (int e = 0; e < 4; e++) Af[t * 4 + e] = aW[e];
    #pragma unroll
    for (int e = 0; e < 8; e++) Bf[t * 8 + e] = bW[e];
    __syncthreads();

    // ---- HMMA aggregation: O[64j x 128d] = P @ Fs, K=64 (4 k-steps), 3 passes.
    // Warp w: m-frag mt = w&3 (16 j's), n-frags nf = (w>>2)*8 + 0..7 (64 d's).
    const int mt = w & 3, nb = w >> 2;
    const int m0 = mt * 16;
    float oacc[8][4];
    #pragma unroll
    for (int j8 = 0; j8 < 8; j8++)
        #pragma unroll
        for (int e = 0; e < 4; e++) oacc[j8][e] = 0.f;

    #pragma unroll
    for (int s = 0; s < 4; s++) {
        uint4 q0 = Af[(m0 + g) * 16 + s * 4 + tt];
        uint4 q1 = Af[(m0 + g + 8) * 16 + s * 4 + tt];
        #pragma unroll
        for (int j8 = 0; j8 < 8; j8++) {
            int drow = (nb * 8 + j8) * 8 + g;
            uint4 B = Bf[drow * 16 + s * 4 + tt];
            mma_bf16(oacc[j8], q0.x, q1.x, q0.y, q1.y, B.x, B.y);   // Ph*Fh
            mma_bf16(oacc[j8], q0.x, q1.x, q0.y, q1.y, B.z, B.w);   // Ph*Fl
            mma_bf16(oacc[j8], q0.z, q1.z, q0.w, q1.w, B.x, B.y);   // Pl*Fh
        }
    }

    float* oh = g_oh + (size_t)bh * FDIM * DOUT;
    #pragma unroll
    for (int j8 = 0; j8 < 8; j8++) {
        int d0 = (nb * 8 + j8) * 8 + 2 * tt;
        *(float2*)&oh[(m0 + g) * 128 + d0]     = make_float2(oacc[j8][0], oacc[j8][1]);
        *(float2*)&oh[(m0 + g + 8) * 128 + d0] = make_float2(oacc[j8][2], oacc[j8][3]);
    }
}

// ---------------------------------------------------------------------------
// Kernel 3: mean over heads + transpose.
// ---------------------------------------------------------------------------
__global__ __launch_bounds__(256)
void reduce_kernel(float* __restrict__ out)
{
    __shared__ float s[64 * 129];
    const int b = blockIdx.x;
    const int t = threadIdx.x;
    const float* oh = g_oh + (size_t)b * HH * FDIM * DOUT;

    for (int idx = t; idx < FDIM * DOUT; idx += 256) {
        int j = idx >> 7, d = idx & 127;
        float v = oh[idx] + oh[idx + 8192] + oh[idx + 16384] + oh[idx + 24576];
        s[j * 129 + d] = 0.25f * v;
    }
    __syncthreads();

    float* ob = out + (size_t)b * DOUT * FDIM;
    for (int idx = t; idx < DOUT * FDIM; idx += 256) {
        int j = idx & 63, d = idx >> 6;
        ob[idx] = s[j * 129 + d];
    }
}

// ---------------------------------------------------------------------------
extern "C" void kernel_launch(void* const* d_in, const int* in_sizes, int n_in,
                              void* d_out, int out_size)
{
    const float* x    = (const float*)d_in[0];
    const float* Wsrc = (const float*)d_in[1];
    const float* bsrc = (const float*)d_in[2];
    const float* Wdst = (const float*)d_in[3];
    const float* bdst = (const float*)d_in[4];
    const float* attn = (const float*)d_in[5];
    float* out = (float*)d_out;

    const int smem2 = (2 * FDIM * NSTRIDE + 128 + 128 + 64 + 64 + 4096) * 4;  // 84480 B

    cudaFuncSetAttribute(attn_kernel, cudaFuncAttributeMaxDynamicSharedMemorySize, smem2);

    conv_w<<<128, 256>>>(Wsrc, Wdst);
    conv_x<<<64, 256>>>(x);
    proj_mma<<<dim3(64, 8), 256>>>(bsrc, bdst);
    attn_kernel<<<BB * HH, 256, smem2>>>(attn);
    reduce_kernel<<<BB, 256>>>(out);
}

// round 16
// speedup vs baseline: 1.0348x; 1.0348x over previous
#include <cuda_runtime.h>
#include <cuda_bf16.h>
#include <cstdint>

typedef unsigned long long ull;

// Problem constants
#define BB    64    // batch
#define WDIM  128   // node feature dim (K of projection)
#define FDIM  64    // number of nodes
#define HH    4     // heads
#define DOUT  128   // out window per head

// Scratch (device globals; allocation-free)
__device__ float g_fs[BB * HH * FDIM * DOUT];   // [b][h][i][d]
__device__ float g_fd[BB * HH * FDIM * DOUT];   // [b][h][j][d]
__device__ float g_oh[BB * HH * FDIM * DOUT];   // [b][h][j][d] per-head outputs

// Fragment-ordered bf16 hi/lo operands for mma.sync m16n8k16.
__device__ uint4 g_a[4096 * 32];   // A = X^T rows [b*64+f], k = w
__device__ uint4 g_w[1024 * 32];   // rows 0..511 = Wsrc, 512..1023 = Wdst

// ---------------------------------------------------------------------------
// f32x2 packed-math helpers
// ---------------------------------------------------------------------------
__device__ __forceinline__ ull fma2(ull a, ull b, ull c) {
    asm("fma.rn.f32x2 %0, %1, %2, %0;" : "+l"(c) : "l"(a), "l"(b));
    return c;
}
__device__ __forceinline__ ull add2(ull a, ull b) {
    ull d; asm("add.rn.f32x2 %0, %1, %2;" : "=l"(d) : "l"(a), "l"(b));
    return d;
}
__device__ __forceinline__ ull dup2(float x) {
    ull d; asm("mov.b64 %0, {%1, %1};" : "=l"(d) : "f"(x));
    return d;
}
__device__ __forceinline__ float2 u2f(ull v) {
    float2 f; asm("mov.b64 {%0, %1}, %2;" : "=f"(f.x), "=f"(f.y) : "l"(v));
    return f;
}
__device__ __forceinline__ ull abs2(ull v) { return v & 0x7fffffff7fffffffULL; }

// ---------------------------------------------------------------------------
// bf16 pack helper: 4 floats -> {hi pair01, hi pair23, lo pair01, lo pair23}
// ---------------------------------------------------------------------------
__device__ __forceinline__ uint4 pack_hilo(float v0, float v1, float v2, float v3) {
    __nv_bfloat16 h0 = __float2bfloat16(v0), h1 = __float2bfloat16(v1);
    __nv_bfloat16 h2 = __float2bfloat16(v2), h3 = __float2bfloat16(v3);
    __nv_bfloat16 l0 = __float2bfloat16(v0 - __bfloat162float(h0));
    __nv_bfloat16 l1 = __float2bfloat16(v1 - __bfloat162float(h1));
    __nv_bfloat16 l2 = __float2bfloat16(v2 - __bfloat162float(h2));
    __nv_bfloat16 l3 = __float2bfloat16(v3 - __bfloat162float(h3));
    uint4 r;
    r.x = (uint32_t)__bfloat16_as_ushort(h0) | ((uint32_t)__bfloat16_as_ushort(h1) << 16);
    r.y = (uint32_t)__bfloat16_as_ushort(h2) | ((uint32_t)__bfloat16_as_ushort(h3) << 16);
    r.z = (uint32_t)__bfloat16_as_ushort(l0) | ((uint32_t)__bfloat16_as_ushort(l1) << 16);
    r.w = (uint32_t)__bfloat16_as_ushort(l2) | ((uint32_t)__bfloat16_as_ushort(l3) << 16);
    return r;
}

// mma.sync m16n8k16 row.col f32.bf16.bf16.f32, accumulate in place
__device__ __forceinline__ void mma_bf16(float* d, uint32_t a0, uint32_t a1,
                                         uint32_t a2, uint32_t a3,
                                         uint32_t b0, uint32_t b1) {
    asm volatile(
        "mma.sync.aligned.m16n8k16.row.col.f32.bf16.bf16.f32 "
        "{%0,%1,%2,%3}, {%4,%5,%6,%7}, {%8,%9}, {%0,%1,%2,%3};"
        : "+f"(d[0]), "+f"(d[1]), "+f"(d[2]), "+f"(d[3])
        : "r"(a0), "r"(a1), "r"(a2), "r"(a3), "r"(b0), "r"(b1));
}

// ---------------------------------------------------------------------------
// conv_wx: merged operand conversion.
// blocks 0..127: W fp32 -> fragment-ordered bf16 hi/lo (g_w).
// blocks 128..191: x[b][w][f] -> A rows [b*64+f][k=w] (g_a), b = blk-128.
// ---------------------------------------------------------------------------
__global__ __launch_bounds__(256)
void conv_wx(const float* __restrict__ x,
             const float* __restrict__ Wsrc, const float* __restrict__ Wdst)
{
    __shared__ float sm[128 * 65];
    const int blk = blockIdx.x, t = threadIdx.x;

    if (blk < 128) {
        int q  = blk * 256 + t;        // 0..32767
        int n  = q >> 5, r5 = q & 31;
        int s  = r5 >> 2, u = r5 & 3;
        int k0 = 16 * s + 2 * u;
        const float* row = (n < 512) ? Wsrc + (size_t)n * 128
                                     : Wdst + (size_t)(n - 512) * 128;
        float2 pa = *(const float2*)(row + k0);
        float2 pb = *(const float2*)(row + k0 + 8);
        g_w[q] = pack_hilo(pa.x, pa.y, pb.x, pb.y);
    } else {
        const int b = blk - 128;
        const float* xb = x + (size_t)b * 8192;
        for (int idx = t; idx < 8192; idx += 256) {
            int w = idx >> 6, f = idx & 63;
            sm[w * 65 + f] = xb[idx];
        }
        __syncthreads();
        #pragma unroll
        for (int it = 0; it < 8; it++) {
            int q  = it * 256 + t;        // 0..2047
            int f  = q >> 5, r5 = q & 31;
            int s  = r5 >> 2, u = r5 & 3;
            int k0 = 16 * s + 2 * u;
            float v0 = sm[(k0)     * 65 + f];
            float v1 = sm[(k0 + 1) * 65 + f];
            float v2 = sm[(k0 + 8) * 65 + f];
            float v3 = sm[(k0 + 9) * 65 + f];
            g_a[(size_t)(b * 64 + f) * 32 + r5] = pack_hilo(v0, v1, v2, v3);
        }
    }
}

// ---------------------------------------------------------------------------
// proj_mma: C[4096,1024] = A @ Wcat^T via bf16 HMMA with hi/lo compensation.
// (unchanged from R11 — validated)
// ---------------------------------------------------------------------------
__global__ __launch_bounds__(256)
void proj_mma(const float* __restrict__ bsrc, const float* __restrict__ bdst)
{
    const int t    = threadIdx.x;
    const int w    = t >> 5;
    const int lane = t & 31;
    const int g    = lane >> 2;
    const int tt   = lane & 3;

    const int rowBase = blockIdx.x * 64  + (w >> 2) * 32;
    const int colBase = blockIdx.y * 128 + (w & 3) * 32;

    float acc[2][4][4];
    #pragma unroll
    for (int mf = 0; mf < 2; mf++)
        #pragma unroll
        for (int nf = 0; nf < 4; nf++)
            #pragma unroll
            for (int e = 0; e < 4; e++) acc[mf][nf][e] = 0.f;

    #pragma unroll
    for (int s = 0; s < 8; s++) {
        uint4 a[2][2];
        #pragma unroll
        for (int mf = 0; mf < 2; mf++) {
            int r0 = rowBase + mf * 16 + g;
            a[mf][0] = g_a[(size_t)r0 * 32 + s * 4 + tt];
            a[mf][1] = g_a[(size_t)(r0 + 8) * 32 + s * 4 + tt];
        }
        uint4 bf[4];
        #pragma unroll
        for (int nf = 0; nf < 4; nf++) {
            int n0 = colBase + nf * 8 + g;
            bf[nf] = g_w[(size_t)n0 * 32 + s * 4 + tt];
        }
        #pragma unroll
        for (int mf = 0; mf < 2; mf++)
            #pragma unroll
            for (int nf = 0; nf < 4; nf++) {
                mma_bf16(acc[mf][nf], a[mf][0].x, a[mf][1].x, a[mf][0].y, a[mf][1].y,
                         bf[nf].x, bf[nf].y);
                mma_bf16(acc[mf][nf], a[mf][0].x, a[mf][1].x, a[mf][0].y, a[mf][1].y,
                         bf[nf].z, bf[nf].w);
                mma_bf16(acc[mf][nf], a[mf][0].z, a[mf][1].z, a[mf][0].w, a[mf][1].w,
                         bf[nf].x, bf[nf].y);
            }
    }

    const bool is_fs = (colBase < 512);
    const float* bias = is_fs ? bsrc : bdst;
    #pragma unroll
    for (int nf = 0; nf < 4; nf++) {
        int cg   = colBase + nf * 8 + 2 * tt;
        int head = (cg >> 7) & 3;
        int d    = cg & 127;
        int bidx = cg & 511;
        float2 bv = *(const float2*)(bias + bidx);
        float* arr = is_fs ? g_fs : g_fd;
        #pragma unroll
        for (int mf = 0; mf < 2; mf++) {
            int r = rowBase + mf * 16 + g;
            int bb = r >> 6, ff = r & 63;
            float* base = arr + ((size_t)(bb * 4 + head) * 64 + ff) * 128 + d;
            *(float2*)base = make_float2(acc[mf][nf][0] + bv.x, acc[mf][nf][1] + bv.y);
            float* base8 = base + 8 * 128;
            *(float2*)base8 = make_float2(acc[mf][nf][2] + bv.x, acc[mf][nf][3] + bv.y);
        }
    }
}

// ---------------------------------------------------------------------------
// Kernel 2: fused scores + softmax + aggregation, one CTA per (b,h).
//
// score = 1.5*(As4[i] + Ad4[j]) + sum_d (0.4 a_d)|fs+fd|, where
// As4 = sum_d (0.4 a_d) fs  (exact rewrite; 0.6 = 1.5*0.4).
//
// fd staged as d-pair-packed, j-contiguous fdT[dp][j] (ull, stride 66):
// the score loop fetches fd for TWO j's with ONE broadcast LDS.128
// (4 loads replace 8).  As/Ad computed by all 256 threads (pair-split
// halves, packed fma2, shfl_xor(1) fold).
// ---------------------------------------------------------------------------
#define NSTRIDE 130

__global__ __launch_bounds__(256, 2)
void attn_kernel(const float* __restrict__ attn)
{
    extern __shared__ float sm[];
    float* fsN   = sm;                        // [64 i][130] fp32     (8320 f)
    ull*   fdT   = (ull*)(sm + 8320);         // [64 dp][66] ull      (8448 f)
    float* attn4 = sm + 16768;                // 128  (0.4 * attn[h])
    float* As_s  = sm + 16896;                // 64
    float* Ad_s  = sm + 16960;                // 64
    float* prob  = sm + 17024;                // [64 j][64 i]         (4096 f)

    const int bh   = blockIdx.x;
    const int h    = bh & 3;
    const int t    = threadIdx.x;
    const int lane = t & 31;
    const int w    = t >> 5;

    const float* fs = g_fs + (size_t)bh * FDIM * DOUT;
    const float* fd = g_fd + (size_t)bh * FDIM * DOUT;

    // Stage: fs row-major (stride 130); fd as fdT[dp][i] d-pair ulls.
    for (int p = t; p < FDIM * 64; p += 256) {
        int i = p >> 6, dp = p & 63;
        *(ull*)&fsN[i * NSTRIDE + 2 * dp] = *(const ull*)&fs[i * DOUT + 2 * dp];
        fdT[dp * 66 + i]                  = *(const ull*)&fd[i * DOUT + 2 * dp];
    }
    if (t < 128) attn4[t] = 0.4f * attn[h * 128 + t];
    __syncthreads();

    // As4[i] = sum_d attn4[d]*fs[i,d];  Ad4[j] likewise (from fdT).
    // Thread pair (t even/odd) splits the d-range; shfl_xor(1) folds.
    {
        int u = t >> 1, hf = t & 1;
        ull s2 = 0ULL;
        if (u < 64) {
            #pragma unroll 8
            for (int dp = hf * 32; dp < hf * 32 + 32; dp++)
                s2 = fma2(*(const ull*)&attn4[2 * dp],
                          *(const ull*)&fsN[u * NSTRIDE + 2 * dp], s2);
        } else {
            int j = u - 64;
            #pragma unroll 8
            for (int dp = hf * 32; dp < hf * 32 + 32; dp++)
                s2 = fma2(*(const ull*)&attn4[2 * dp], fdT[dp * 66 + j], s2);
        }
        float2 f2 = u2f(s2);
        float s = f2.x + f2.y;
        s += __shfl_xor_sync(0xffffffffu, s, 1);
        if (hf == 0) { if (u < 64) As_s[u] = s; else Ad_s[u - 64] = s; }
    }
    __syncthreads();

    // ---- Score phase: warp w owns j = w*8..w*8+7; lane owns i = lane, lane+32.
    const int jb = w * 8;
    const int i0 = lane, i1 = lane + 32;
    ull acc0[8], acc1[8];
    #pragma unroll
    for (int jj = 0; jj < 8; jj++) { acc0[jj] = 0ULL; acc1[jj] = 0ULL; }

    #pragma unroll 2
    for (int dp = 0; dp < 64; dp++) {
        ull a42 = *(const ull*)&attn4[2 * dp];                 // broadcast
        ull f20 = *(const ull*)&fsN[i0 * NSTRIDE + 2 * dp];
        ull f21 = *(const ull*)&fsN[i1 * NSTRIDE + 2 * dp];
        #pragma unroll
        for (int jp = 0; jp < 4; jp++) {
            // one broadcast LDS.128 = fd pairs for j = jb+2jp and jb+2jp+1
            ulonglong2 q = *(const ulonglong2*)&fdT[dp * 66 + jb + 2 * jp];
            acc0[2 * jp]     = fma2(a42, abs2(add2(f20, q.x)), acc0[2 * jp]);
            acc1[2 * jp]     = fma2(a42, abs2(add2(f21, q.x)), acc1[2 * jp]);
            acc0[2 * jp + 1] = fma2(a42, abs2(add2(f20, q.y)), acc0[2 * jp + 1]);
            acc1[2 * jp + 1] = fma2(a42, abs2(add2(f21, q.y)), acc1[2 * jp + 1]);
        }
    }

    // ---- Softmax over i (64 sources) per j  (note 1.5 = 0.6/0.4 rescale)
    const float As0 = As_s[i0], As1 = As_s[i1];
    #pragma unroll
    for (int jj = 0; jj < 8; jj++) {
        float Adv = Ad_s[jb + jj];
        float2 h0 = u2f(acc0[jj]);
        float2 h1 = u2f(acc1[jj]);
        float s0 = 1.5f * (As0 + Adv) + (h0.x + h0.y);
        float s1 = 1.5f * (As1 + Adv) + (h1.x + h1.y);
        float m = fmaxf(s0, s1);
        #pragma unroll
        for (int o = 16; o; o >>= 1) m = fmaxf(m, __shfl_xor_sync(0xffffffffu, m, o));
        float e0 = __expf(s0 - m);
        float e1 = __expf(s1 - m);
        float ssum = e0 + e1;
        #pragma unroll
        for (int o = 16; o; o >>= 1) ssum += __shfl_xor_sync(0xffffffffu, ssum, o);
        float inv = __frcp_rn(ssum);
        prob[(jb + jj) * 64 + i0] = e0 * inv;
        prob[(jb + jj) * 64 + i1] = e1 * inv;
    }
    __syncwarp();

    // ---- Aggregation (R11 idiom): lane owns d-pairs at 2*lane, 2*(lane+32).
    ull o2[8][2];
    #pragma unroll
    for (int jj = 0; jj < 8; jj++) { o2[jj][0] = 0ULL; o2[jj][1] = 0ULL; }

    #pragma unroll 2
    for (int i = 0; i < 64; i++) {
        ull f20 = *(const ull*)&fsN[i * NSTRIDE + 2 * lane];
        ull f21 = *(const ull*)&fsN[i * NSTRIDE + 2 * (lane + 32)];
        #pragma unroll
        for (int jj = 0; jj < 8; jj++) {
            ull pd = dup2(prob[(jb + jj) * 64 + i]);
            o2[jj][0] = fma2(pd, f20, o2[jj][0]);
            o2[jj][1] = fma2(pd, f21, o2[jj][1]);
        }
    }

    float* oh = g_oh + (size_t)bh * FDIM * DOUT;
    #pragma unroll
    for (int jj = 0; jj < 8; jj++) {
        *(float2*)&oh[(jb + jj) * DOUT + 2 * lane]        = u2f(o2[jj][0]);
        *(float2*)&oh[(jb + jj) * DOUT + 2 * (lane + 32)] = u2f(o2[jj][1]);
    }
}

// ---------------------------------------------------------------------------
// Kernel 3: mean over heads + transpose.
// ---------------------------------------------------------------------------
__global__ __launch_bounds__(256)
void reduce_kernel(float* __restrict__ out)
{
    __shared__ float s[64 * 129];
    const int b = blockIdx.x;
    const int t = threadIdx.x;
    const float* oh = g_oh + (size_t)b * HH * FDIM * DOUT;

    for (int idx = t; idx < FDIM * DOUT; idx += 256) {
        int j = idx >> 7, d = idx & 127;
        float v = oh[idx] + oh[idx + 8192] + oh[idx + 16384] + oh[idx + 24576];
        s[j * 129 + d] = 0.25f * v;
    }
    __syncthreads();

    float* ob = out + (size_t)b * DOUT * FDIM;
    for (int idx = t; idx < DOUT * FDIM; idx += 256) {
        int j = idx & 63, d = idx >> 6;
        ob[idx] = s[j * 129 + d];
    }
}

// ---------------------------------------------------------------------------
extern "C" void kernel_launch(void* const* d_in, const int* in_sizes, int n_in,
                              void* d_out, int out_size)
{
    const float* x    = (const float*)d_in[0];
    const float* Wsrc = (const float*)d_in[1];
    const float* bsrc = (const float*)d_in[2];
    const float* Wdst = (const float*)d_in[3];
    const float* bdst = (const float*)d_in[4];
    const float* attn = (const float*)d_in[5];
    float* out = (float*)d_out;

    const int smem2 = (8320 + 8448 + 128 + 64 + 64 + 4096) * 4;   // 84480 B

    cudaFuncSetAttribute(attn_kernel, cudaFuncAttributeMaxDynamicSharedMemorySize, smem2);

    conv_wx<<<192, 256>>>(x, Wsrc, Wdst);
    proj_mma<<<dim3(64, 8), 256>>>(bsrc, bdst);
    attn_kernel<<<BB * HH, 256, smem2>>>(attn);
    reduce_kernel<<<BB, 256>>>(out);
}

// round 17
// speedup vs baseline: 1.0734x; 1.0373x over previous
#include <cuda_runtime.h>
#include <cuda_bf16.h>
#include <cstdint>

typedef unsigned long long ull;

// Problem constants
#define BB    64    // batch
#define WDIM  128   // node feature dim (K of projection)
#define FDIM  64    // number of nodes
#define HH    4     // heads
#define DOUT  128   // out window per head

// Scratch (device globals; allocation-free)
__device__ float g_fs[BB * HH * FDIM * DOUT];   // [b][h][i][d]
__device__ float g_fd[BB * HH * FDIM * DOUT];   // [b][h][j][d]
__device__ float g_oh[BB * HH * FDIM * DOUT];   // [b][h][j][d] per-head outputs

// Fragment-ordered bf16 hi/lo operands for mma.sync m16n8k16.
__device__ uint4 g_a[4096 * 32];   // A = X^T rows [b*64+f], k = w
__device__ uint4 g_w[1024 * 32];   // rows 0..511 = Wsrc, 512..1023 = Wdst

// ---------------------------------------------------------------------------
// f32x2 packed-math helpers
// ---------------------------------------------------------------------------
__device__ __forceinline__ ull fma2(ull a, ull b, ull c) {
    asm("fma.rn.f32x2 %0, %1, %2, %0;" : "+l"(c) : "l"(a), "l"(b));
    return c;
}
__device__ __forceinline__ ull add2(ull a, ull b) {
    ull d; asm("add.rn.f32x2 %0, %1, %2;" : "=l"(d) : "l"(a), "l"(b));
    return d;
}
__device__ __forceinline__ ull dup2(float x) {
    ull d; asm("mov.b64 %0, {%1, %1};" : "=l"(d) : "f"(x));
    return d;
}
__device__ __forceinline__ float2 u2f(ull v) {
    float2 f; asm("mov.b64 {%0, %1}, %2;" : "=f"(f.x), "=f"(f.y) : "l"(v));
    return f;
}
__device__ __forceinline__ ull abs2(ull v) { return v & 0x7fffffff7fffffffULL; }

// ---------------------------------------------------------------------------
// bf16 pack helper: 4 floats -> {hi pair01, hi pair23, lo pair01, lo pair23}
// ---------------------------------------------------------------------------
__device__ __forceinline__ uint4 pack_hilo(float v0, float v1, float v2, float v3) {
    __nv_bfloat16 h0 = __float2bfloat16(v0), h1 = __float2bfloat16(v1);
    __nv_bfloat16 h2 = __float2bfloat16(v2), h3 = __float2bfloat16(v3);
    __nv_bfloat16 l0 = __float2bfloat16(v0 - __bfloat162float(h0));
    __nv_bfloat16 l1 = __float2bfloat16(v1 - __bfloat162float(h1));
    __nv_bfloat16 l2 = __float2bfloat16(v2 - __bfloat162float(h2));
    __nv_bfloat16 l3 = __float2bfloat16(v3 - __bfloat162float(h3));
    uint4 r;
    r.x = (uint32_t)__bfloat16_as_ushort(h0) | ((uint32_t)__bfloat16_as_ushort(h1) << 16);
    r.y = (uint32_t)__bfloat16_as_ushort(h2) | ((uint32_t)__bfloat16_as_ushort(h3) << 16);
    r.z = (uint32_t)__bfloat16_as_ushort(l0) | ((uint32_t)__bfloat16_as_ushort(l1) << 16);
    r.w = (uint32_t)__bfloat16_as_ushort(l2) | ((uint32_t)__bfloat16_as_ushort(l3) << 16);
    return r;
}

// mma.sync m16n8k16 row.col f32.bf16.bf16.f32, accumulate in place
__device__ __forceinline__ void mma_bf16(float* d, uint32_t a0, uint32_t a1,
                                         uint32_t a2, uint32_t a3,
                                         uint32_t b0, uint32_t b1) {
    asm volatile(
        "mma.sync.aligned.m16n8k16.row.col.f32.bf16.bf16.f32 "
        "{%0,%1,%2,%3}, {%4,%5,%6,%7}, {%8,%9}, {%0,%1,%2,%3};"
        : "+f"(d[0]), "+f"(d[1]), "+f"(d[2]), "+f"(d[3])
        : "r"(a0), "r"(a1), "r"(a2), "r"(a3), "r"(b0), "r"(b1));
}

// ---------------------------------------------------------------------------
// conv_wx: merged operand conversion.
// blocks 0..127: W fp32 -> fragment-ordered bf16 hi/lo (g_w).
// blocks 128..191: x[b][w][f] -> A rows [b*64+f][k=w] (g_a), b = blk-128.
// ---------------------------------------------------------------------------
__global__ __launch_bounds__(256)
void conv_wx(const float* __restrict__ x,
             const float* __restrict__ Wsrc, const float* __restrict__ Wdst)
{
    __shared__ float sm[128 * 65];
    const int blk = blockIdx.x, t = threadIdx.x;

    if (blk < 128) {
        int q  = blk * 256 + t;        // 0..32767
        int n  = q >> 5, r5 = q & 31;
        int s  = r5 >> 2, u = r5 & 3;
        int k0 = 16 * s + 2 * u;
        const float* row = (n < 512) ? Wsrc + (size_t)n * 128
                                     : Wdst + (size_t)(n - 512) * 128;
        float2 pa = *(const float2*)(row + k0);
        float2 pb = *(const float2*)(row + k0 + 8);
        g_w[q] = pack_hilo(pa.x, pa.y, pb.x, pb.y);
    } else {
        const int b = blk - 128;
        const float* xb = x + (size_t)b * 8192;
        for (int idx = t; idx < 8192; idx += 256) {
            int w = idx >> 6, f = idx & 63;
            sm[w * 65 + f] = xb[idx];
        }
        __syncthreads();
        #pragma unroll
        for (int it = 0; it < 8; it++) {
            int q  = it * 256 + t;        // 0..2047
            int f  = q >> 5, r5 = q & 31;
            int s  = r5 >> 2, u = r5 & 3;
            int k0 = 16 * s + 2 * u;
            float v0 = sm[(k0)     * 65 + f];
            float v1 = sm[(k0 + 1) * 65 + f];
            float v2 = sm[(k0 + 8) * 65 + f];
            float v3 = sm[(k0 + 9) * 65 + f];
            g_a[(size_t)(b * 64 + f) * 32 + r5] = pack_hilo(v0, v1, v2, v3);
        }
    }
}

// ---------------------------------------------------------------------------
// proj_mma: C[4096,1024] = A @ Wcat^T via bf16 HMMA with hi/lo compensation.
// (unchanged from R11 — validated)
// ---------------------------------------------------------------------------
__global__ __launch_bounds__(256)
void proj_mma(const float* __restrict__ bsrc, const float* __restrict__ bdst)
{
    const int t    = threadIdx.x;
    const int w    = t >> 5;
    const int lane = t & 31;
    const int g    = lane >> 2;
    const int tt   = lane & 3;

    const int rowBase = blockIdx.x * 64  + (w >> 2) * 32;
    const int colBase = blockIdx.y * 128 + (w & 3) * 32;

    float acc[2][4][4];
    #pragma unroll
    for (int mf = 0; mf < 2; mf++)
        #pragma unroll
        for (int nf = 0; nf < 4; nf++)
            #pragma unroll
            for (int e = 0; e < 4; e++) acc[mf][nf][e] = 0.f;

    #pragma unroll
    for (int s = 0; s < 8; s++) {
        uint4 a[2][2];
        #pragma unroll
        for (int mf = 0; mf < 2; mf++) {
            int r0 = rowBase + mf * 16 + g;
            a[mf][0] = g_a[(size_t)r0 * 32 + s * 4 + tt];
            a[mf][1] = g_a[(size_t)(r0 + 8) * 32 + s * 4 + tt];
        }
        uint4 bf[4];
        #pragma unroll
        for (int nf = 0; nf < 4; nf++) {
            int n0 = colBase + nf * 8 + g;
            bf[nf] = g_w[(size_t)n0 * 32 + s * 4 + tt];
        }
        #pragma unroll
        for (int mf = 0; mf < 2; mf++)
            #pragma unroll
            for (int nf = 0; nf < 4; nf++) {
                mma_bf16(acc[mf][nf], a[mf][0].x, a[mf][1].x, a[mf][0].y, a[mf][1].y,
                         bf[nf].x, bf[nf].y);
                mma_bf16(acc[mf][nf], a[mf][0].x, a[mf][1].x, a[mf][0].y, a[mf][1].y,
                         bf[nf].z, bf[nf].w);
                mma_bf16(acc[mf][nf], a[mf][0].z, a[mf][1].z, a[mf][0].w, a[mf][1].w,
                         bf[nf].x, bf[nf].y);
            }
    }

    const bool is_fs = (colBase < 512);
    const float* bias = is_fs ? bsrc : bdst;
    #pragma unroll
    for (int nf = 0; nf < 4; nf++) {
        int cg   = colBase + nf * 8 + 2 * tt;
        int head = (cg >> 7) & 3;
        int d    = cg & 127;
        int bidx = cg & 511;
        float2 bv = *(const float2*)(bias + bidx);
        float* arr = is_fs ? g_fs : g_fd;
        #pragma unroll
        for (int mf = 0; mf < 2; mf++) {
            int r = rowBase + mf * 16 + g;
            int bb = r >> 6, ff = r & 63;
            float* base = arr + ((size_t)(bb * 4 + head) * 64 + ff) * 128 + d;
            *(float2*)base = make_float2(acc[mf][nf][0] + bv.x, acc[mf][nf][1] + bv.y);
            float* base8 = base + 8 * 128;
            *(float2*)base8 = make_float2(acc[mf][nf][2] + bv.x, acc[mf][nf][3] + bv.y);
        }
    }
}

// ---------------------------------------------------------------------------
// Kernel 2: fused scores + softmax + aggregation, one CTA per (b,h).
// (unchanged from R16 — equal-best measured)
// ---------------------------------------------------------------------------
#define NSTRIDE 130

__global__ __launch_bounds__(256, 2)
void attn_kernel(const float* __restrict__ attn)
{
    extern __shared__ float sm[];
    float* fsN   = sm;                        // [64 i][130] fp32     (8320 f)
    ull*   fdT   = (ull*)(sm + 8320);         // [64 dp][66] ull      (8448 f)
    float* attn4 = sm + 16768;                // 128  (0.4 * attn[h])
    float* As_s  = sm + 16896;                // 64
    float* Ad_s  = sm + 16960;                // 64
    float* prob  = sm + 17024;                // [64 j][64 i]         (4096 f)

    const int bh   = blockIdx.x;
    const int h    = bh & 3;
    const int t    = threadIdx.x;
    const int lane = t & 31;
    const int w    = t >> 5;

    const float* fs = g_fs + (size_t)bh * FDIM * DOUT;
    const float* fd = g_fd + (size_t)bh * FDIM * DOUT;

    // Stage: fs row-major (stride 130); fd as fdT[dp][i] d-pair ulls.
    for (int p = t; p < FDIM * 64; p += 256) {
        int i = p >> 6, dp = p & 63;
        *(ull*)&fsN[i * NSTRIDE + 2 * dp] = *(const ull*)&fs[i * DOUT + 2 * dp];
        fdT[dp * 66 + i]                  = *(const ull*)&fd[i * DOUT + 2 * dp];
    }
    if (t < 128) attn4[t] = 0.4f * attn[h * 128 + t];
    __syncthreads();

    // As4[i] = sum_d attn4[d]*fs[i,d];  Ad4[j] likewise (from fdT).
    {
        int u = t >> 1, hf = t & 1;
        ull s2 = 0ULL;
        if (u < 64) {
            #pragma unroll 8
            for (int dp = hf * 32; dp < hf * 32 + 32; dp++)
                s2 = fma2(*(const ull*)&attn4[2 * dp],
                          *(const ull*)&fsN[u * NSTRIDE + 2 * dp], s2);
        } else {
            int j = u - 64;
            #pragma unroll 8
            for (int dp = hf * 32; dp < hf * 32 + 32; dp++)
                s2 = fma2(*(const ull*)&attn4[2 * dp], fdT[dp * 66 + j], s2);
        }
        float2 f2 = u2f(s2);
        float s = f2.x + f2.y;
        s += __shfl_xor_sync(0xffffffffu, s, 1);
        if (hf == 0) { if (u < 64) As_s[u] = s; else Ad_s[u - 64] = s; }
    }
    __syncthreads();

    // ---- Score phase: warp w owns j = w*8..w*8+7; lane owns i = lane, lane+32.
    const int jb = w * 8;
    const int i0 = lane, i1 = lane + 32;
    ull acc0[8], acc1[8];
    #pragma unroll
    for (int jj = 0; jj < 8; jj++) { acc0[jj] = 0ULL; acc1[jj] = 0ULL; }

    #pragma unroll 2
    for (int dp = 0; dp < 64; dp++) {
        ull a42 = *(const ull*)&attn4[2 * dp];                 // broadcast
        ull f20 = *(const ull*)&fsN[i0 * NSTRIDE + 2 * dp];
        ull f21 = *(const ull*)&fsN[i1 * NSTRIDE + 2 * dp];
        #pragma unroll
        for (int jp = 0; jp < 4; jp++) {
            ulonglong2 q = *(const ulonglong2*)&fdT[dp * 66 + jb + 2 * jp];
            acc0[2 * jp]     = fma2(a42, abs2(add2(f20, q.x)), acc0[2 * jp]);
            acc1[2 * jp]     = fma2(a42, abs2(add2(f21, q.x)), acc1[2 * jp]);
            acc0[2 * jp + 1] = fma2(a42, abs2(add2(f20, q.y)), acc0[2 * jp + 1]);
            acc1[2 * jp + 1] = fma2(a42, abs2(add2(f21, q.y)), acc1[2 * jp + 1]);
        }
    }

    // ---- Softmax over i (64 sources) per j  (1.5 = 0.6/0.4 rescale)
    const float As0 = As_s[i0], As1 = As_s[i1];
    #pragma unroll
    for (int jj = 0; jj < 8; jj++) {
        float Adv = Ad_s[jb + jj];
        float2 h0 = u2f(acc0[jj]);
        float2 h1 = u2f(acc1[jj]);
        float s0 = 1.5f * (As0 + Adv) + (h0.x + h0.y);
        float s1 = 1.5f * (As1 + Adv) + (h1.x + h1.y);
        float m = fmaxf(s0, s1);
        #pragma unroll
        for (int o = 16; o; o >>= 1) m = fmaxf(m, __shfl_xor_sync(0xffffffffu, m, o));
        float e0 = __expf(s0 - m);
        float e1 = __expf(s1 - m);
        float ssum = e0 + e1;
        #pragma unroll
        for (int o = 16; o; o >>= 1) ssum += __shfl_xor_sync(0xffffffffu, ssum, o);
        float inv = __frcp_rn(ssum);
        prob[(jb + jj) * 64 + i0] = e0 * inv;
        prob[(jb + jj) * 64 + i1] = e1 * inv;
    }
    __syncwarp();

    // ---- Aggregation: lane owns d-pairs at 2*lane, 2*(lane+32).
    ull o2[8][2];
    #pragma unroll
    for (int jj = 0; jj < 8; jj++) { o2[jj][0] = 0ULL; o2[jj][1] = 0ULL; }

    #pragma unroll 2
    for (int i = 0; i < 64; i++) {
        ull f20 = *(const ull*)&fsN[i * NSTRIDE + 2 * lane];
        ull f21 = *(const ull*)&fsN[i * NSTRIDE + 2 * (lane + 32)];
        #pragma unroll
        for (int jj = 0; jj < 8; jj++) {
            ull pd = dup2(prob[(jb + jj) * 64 + i]);
            o2[jj][0] = fma2(pd, f20, o2[jj][0]);
            o2[jj][1] = fma2(pd, f21, o2[jj][1]);
        }
    }

    float* oh = g_oh + (size_t)bh * FDIM * DOUT;
    #pragma unroll
    for (int jj = 0; jj < 8; jj++) {
        *(float2*)&oh[(jb + jj) * DOUT + 2 * lane]        = u2f(o2[jj][0]);
        *(float2*)&oh[(jb + jj) * DOUT + 2 * (lane + 32)] = u2f(o2[jj][1]);
    }
}

// ---------------------------------------------------------------------------
// Kernel 3: mean over heads + transpose — 4-way split for chip fill.
// grid (64 b, 4 jq); CTA handles 16 j's: out[b, d, jq*16+jj] =
// 0.25 * sum_h oh[b,h,j,d].  float4 loads, 16x132 smem tile (conflict-free),
// float4 transposed stores.
// ---------------------------------------------------------------------------
__global__ __launch_bounds__(256)
void reduce_kernel(float* __restrict__ out)
{
    __shared__ float s[16 * 132];
    const int b = blockIdx.x, jq = blockIdx.y;
    const int t = threadIdx.x;
    const float* oh = g_oh + (size_t)b * HH * FDIM * DOUT + jq * 16 * DOUT;

    // Load + head-sum: 16 j x 128 d = 512 float4; 2 iters/thread, 8 LDG.128 each
    #pragma unroll
    for (int it = 0; it < 2; it++) {
        int idx = it * 256 + t;            // 0..511
        int j = idx >> 5, c = idx & 31;    // c = float4 column
        const float4* p0 = (const float4*)(oh + j * DOUT) + c;
        float4 v0 = p0[0];
        float4 v1 = p0[2048];              // +8192 floats (head 1)
        float4 v2 = p0[4096];
        float4 v3 = p0[6144];
        float4 r;
        r.x = 0.25f * (v0.x + v1.x + v2.x + v3.x);
        r.y = 0.25f * (v0.y + v1.y + v2.y + v3.y);
        r.z = 0.25f * (v0.z + v1.z + v2.z + v3.z);
        r.w = 0.25f * (v0.w + v1.w + v2.w + v3.w);
        *(float4*)&s[j * 132 + c * 4] = r;
    }
    __syncthreads();

    // Transposed store: 128 d x 16 j = 512 float4 (4 j's per float4)
    float* ob = out + (size_t)b * DOUT * FDIM + jq * 16;
    #pragma unroll
    for (int it = 0; it < 2; it++) {
        int idx = it * 256 + t;            // 0..511
        int d = idx >> 2, jc = idx & 3;    // jc = group of 4 j's
        float4 o;
        o.x = s[(jc * 4 + 0) * 132 + d];
        o.y = s[(jc * 4 + 1) * 132 + d];
        o.z = s[(jc * 4 + 2) * 132 + d];
        o.w = s[(jc * 4 + 3) * 132 + d];
        *(float4*)(ob + d * FDIM + jc * 4) = o;
    }
}

// ---------------------------------------------------------------------------
extern "C" void kernel_launch(void* const* d_in, const int* in_sizes, int n_in,
                              void* d_out, int out_size)
{
    const float* x    = (const float*)d_in[0];
    const float* Wsrc = (const float*)d_in[1];
    const float* bsrc = (const float*)d_in[2];
    const float* Wdst = (const float*)d_in[3];
    const float* bdst = (const float*)d_in[4];
    const float* attn = (const float*)d_in[5];
    float* out = (float*)d_out;

    const int smem2 = (8320 + 8448 + 128 + 64 + 64 + 4096) * 4;   // 84480 B

    cudaFuncSetAttribute(attn_kernel, cudaFuncAttributeMaxDynamicSharedMemorySize, smem2);

    conv_wx<<<192, 256>>>(x, Wsrc, Wdst);
    proj_mma<<<dim3(64, 8), 256>>>(bsrc, bdst);
    attn_kernel<<<BB * HH, 256, smem2>>>(attn);
    reduce_kernel<<<dim3(BB, 4), 256>>>(out);
}